// round 14
// baseline (speedup 1.0000x reference)
#include <cuda_runtime.h>

// MatchAttention fused forward, fixed shape:
// B=2, H=W=64, N=4096, C=256, heads=8, Ch=32, r=3 -> K=49, scale=1, l1_norm.
#define HH   64
#define WW   64
#define CC   256
#define NHD  8
#define CH   32
#define RR   3
#define KWIN 49
#define NPIX (HH * WW)

// Split gather: one fetch = two complementary-predicated coherent LDG.128s.
// Lanes 0-15 (head groups 0,1) load in the first, lanes 16-31 in the second;
// each LDG touches 2 cache lines instead of 4, cutting within-LDG wavefront
// replay serialization. Plain ld.global (default caching — R13's .nc variant
// demoted the gathers to streaming and blew up DRAM), no volatile (keeps
// ptxas scheduling freedom).
__device__ __forceinline__ float4 ldg_split(const float* ptr, int isLow) {
    float4 r;
    asm("{\n\t"
        ".reg .pred lo, hi;\n\t"
        "setp.ne.s32 lo, %5, 0;\n\t"
        "setp.eq.s32 hi, %5, 0;\n\t"
        "@lo ld.global.v4.f32 {%0,%1,%2,%3}, [%4];\n\t"
        "@hi ld.global.v4.f32 {%0,%1,%2,%3}, [%4];\n\t"
        "}"
        : "=f"(r.x), "=f"(r.y), "=f"(r.z), "=f"(r.w)
        : "l"(ptr), "r"(isLow));
    return r;
}

// One warp = 4 heads of one pixel (8 lanes/head, 4 channels/lane) — R5 core.
// Streaming softmax with fixed reference (sim <= 0 always; d ~ 36+/-5 so
// exp(-d) is far above fp32 underflow); final 1/sum rescale == reference.
__global__ __launch_bounds__(256, 4)
void match_attn_kernel(const float* __restrict__ moff,   // [B,N,h,2]
                       const float* __restrict__ qp,     // [B,N,C]
                       const float* __restrict__ kp,     // [B,N,C]
                       const float* __restrict__ vp,     // [B,N,C]
                       float* __restrict__ out,          // [B,N,C]
                       float* __restrict__ attn_out)     // [B,N,h,K]
{
    const int warpGlobal = (blockIdx.x * blockDim.x + threadIdx.x) >> 5;
    const int lane = threadIdx.x & 31;
    const int lig  = lane & 7;    // lane within 8-lane head group
    const int grp  = lane >> 3;   // head-in-half

    const int p = warpGlobal >> 1;               // global pixel (incl batch)
    const int g = (warpGlobal & 1) * 4 + grp;    // head id

    const int n    = p & (NPIX - 1);
    const int base = p - n;                      // b*N
    const int y    = n / WW;
    const int x    = n & (WW - 1);

    // rounded per-head window center (rintf == jnp.round, half-to-even)
    const float2 off2 = *(const float2*)&moff[(size_t)(p * NHD + g) * 2];
    const int cy = y + (int)rintf(off2.x);
    const int cx = x + (int)rintf(off2.y);

    const int chBase = g * CH + lig * 4;

    // clamped row/col element-offsets; chBase folded into the row term
    int pyW[7], pxc[7];
#pragma unroll
    for (int i = 0; i < 7; i++) {
        const int py = min(max(cy + i - RR, 0), HH - 1);
        const int px = min(max(cx + i - RR, 0), WW - 1);
        pyW[i] = (base + py * WW) * CC + chBase;
        pxc[i] = px * CC;
    }

    const float4 q4 = *(const float4*)(qp + (size_t)p * CC + chBase);

    const bool b0 = (lig & 1) != 0;
    const bool b1 = (lig & 2) != 0;
    const bool b2 = (lig & 4) != 0;
    const int  gbase = lane & 24;   // first lane of this head group
    const int  isLow = (lane < 16) ? 1 : 0;

    float w_own[6];
    float s = 0.f;
    float4 acc = make_float4(0.f, 0.f, 0.f, 0.f);

#pragma unroll
    for (int j = 0; j < 6; j++) {
        // ---- shared addresses for this group (k and v gathers) --------------
        int offs[8];
#pragma unroll
        for (int t = 0; t < 8; t++) {
            const int kk = j * 8 + t;
            offs[t] = pyW[kk / 7] + pxc[kk % 7];
        }

        // ---- 8 k-gathers (split: 2 lines per LDG) + partial L1 distances -----
        float pd[8];
#pragma unroll
        for (int t = 0; t < 8; t++) {
            const float4 k4 = ldg_split(kp + offs[t], isLow);
            pd[t] = fabsf(q4.x - k4.x) + fabsf(q4.y - k4.y)
                  + fabsf(q4.z - k4.z) + fabsf(q4.w - k4.w);
        }

        // ---- transposed butterfly: lane lig ends with full d of slot 8j+lig --
        float r4[4];
#pragma unroll
        for (int t = 0; t < 4; t++) {
            const float keep = b0 ? pd[2 * t + 1] : pd[2 * t];
            const float send = b0 ? pd[2 * t]     : pd[2 * t + 1];
            r4[t] = keep + __shfl_xor_sync(0xffffffffu, send, 1);
        }
        float r2[2];
#pragma unroll
        for (int t = 0; t < 2; t++) {
            const float keep = b1 ? r4[2 * t + 1] : r4[2 * t];
            const float send = b1 ? r4[2 * t]     : r4[2 * t + 1];
            r2[t] = keep + __shfl_xor_sync(0xffffffffu, send, 2);
        }
        const float keep = b2 ? r2[1] : r2[0];
        const float send = b2 ? r2[0] : r2[1];
        const float d = keep + __shfl_xor_sync(0xffffffffu, send, 4);

        const float w = __expf(-d);   // weight of owned slot 8j+lig
        s += w;
        w_own[j] = w;

        // ---- v accumulation (split gathers): broadcast w from owner lane ----
#pragma unroll
        for (int t = 0; t < 8; t++) {
            const float wt = __shfl_sync(0xffffffffu, w, gbase | t);
            const float4 v4 = ldg_split(vp + offs[t], isLow);
            acc.x = fmaf(wt, v4.x, acc.x);
            acc.y = fmaf(wt, v4.y, acc.y);
            acc.z = fmaf(wt, v4.z, acc.z);
            acc.w = fmaf(wt, v4.w, acc.w);
        }
    }

    // ---- remainder slot 48 (row 6, col 6) ------------------------------------
    float w48;
    {
        const int off48 = pyW[6] + pxc[6];
        const float4 k4 = ldg_split(kp + off48, isLow);
        float d = fabsf(q4.x - k4.x) + fabsf(q4.y - k4.y)
                + fabsf(q4.z - k4.z) + fabsf(q4.w - k4.w);
        d += __shfl_xor_sync(0xffffffffu, d, 1);
        d += __shfl_xor_sync(0xffffffffu, d, 2);
        d += __shfl_xor_sync(0xffffffffu, d, 4);
        w48 = __expf(-d);                        // full weight on all 8 lanes
        const float4 v4 = ldg_split(vp + off48, isLow);
        acc.x = fmaf(w48, v4.x, acc.x);
        acc.y = fmaf(w48, v4.y, acc.y);
        acc.z = fmaf(w48, v4.z, acc.z);
        acc.w = fmaf(w48, v4.w, acc.w);
    }

    // ---- normalization --------------------------------------------------------
    s += __shfl_xor_sync(0xffffffffu, s, 1);
    s += __shfl_xor_sync(0xffffffffu, s, 2);
    s += __shfl_xor_sync(0xffffffffu, s, 4);
    s += w48;
    const float inv = 1.f / s;

    float* aout = attn_out + (size_t)(p * NHD + g) * KWIN;
#pragma unroll
    for (int j = 0; j < 6; j++) aout[j * 8 + lig] = w_own[j] * inv;
    if (lig == 0) aout[48] = w48 * inv;

    acc.x *= inv; acc.y *= inv; acc.z *= inv; acc.w *= inv;
    *(float4*)(out + (size_t)p * CC + chBase) = acc;
}

extern "C" void kernel_launch(void* const* d_in, const int* in_sizes, int n_in,
                              void* d_out, int out_size) {
    const float* moff = (const float*)d_in[0];   // [B,N,h,2]
    const float* q    = (const float*)d_in[1];   // [B,N,C]
    const float* k    = (const float*)d_in[2];
    const float* v    = (const float*)d_in[3];

    float* out = (float*)d_out;                  // output [B,N,C] first...
    const int qElems = in_sizes[1];              // B*N*C
    float* attn_out = out + qElems;              // ...then attn_out [B,N,h,K]

    const int items = in_sizes[0] / 2;           // B*N*h
    const int totalWarps = items / 4;            // 4 heads per warp
    const int threads = 256;
    const int blocks = (totalWarps * 32) / threads;   // 2048

    match_attn_kernel<<<blocks, threads>>>(moff, q, k, v, out, attn_out);
}

// round 15
// speedup vs baseline: 6.2642x; 6.2642x over previous
#include <cuda_runtime.h>

// MatchAttention fused forward, fixed shape:
// B=2, H=W=64, N=4096, C=256, heads=8, Ch=32, r=3 -> K=49, scale=1, l1_norm.
//
// FINAL (R15 = R5, the measured optimum of 14 variants at 47.6us):
// One warp = 4 heads of one pixel (8 lanes/head, 4 channels/lane).
// Slots in 6 groups of 8 + 1 remainder; per group a transposed 3-round
// butterfly leaves lane `lig` holding the FULL L1 distance of slot 8j+lig,
// and only the owner lane runs exp. Streaming softmax with fixed reference
// (sim <= 0 always; d ~ 36+/-5 so exp(-d) is far above fp32 underflow);
// final 1/sum rescale is exactly the reference softmax.
//
// Cost model (validated across rounds): 98 gather LDG.128/warp, each touching
// 4 cache lines (one per head group) -> ~390 L1 wavefronts/warp; this L1
// gather wavefront service is the binding resource. Occupancy, instruction
// count, ILP, pipelining, locality and load-splitting variants all proved
// neutral or worse against this floor.
#define HH   64
#define WW   64
#define CC   256
#define NHD  8
#define CH   32
#define RR   3
#define KWIN 49
#define NPIX (HH * WW)

__global__ __launch_bounds__(256, 4)
void match_attn_kernel(const float* __restrict__ moff,   // [B,N,h,2]
                       const float* __restrict__ qp,     // [B,N,C]
                       const float* __restrict__ kp,     // [B,N,C]
                       const float* __restrict__ vp,     // [B,N,C]
                       float* __restrict__ out,          // [B,N,C]
                       float* __restrict__ attn_out)     // [B,N,h,K]
{
    const int warpGlobal = (blockIdx.x * blockDim.x + threadIdx.x) >> 5;
    const int lane = threadIdx.x & 31;
    const int lig  = lane & 7;    // lane within 8-lane head group
    const int grp  = lane >> 3;   // head-in-half

    const int p = warpGlobal >> 1;               // global pixel (incl batch)
    const int g = (warpGlobal & 1) * 4 + grp;    // head id

    const int n    = p & (NPIX - 1);
    const int base = p - n;                      // b*N
    const int y    = n / WW;
    const int x    = n & (WW - 1);

    // rounded per-head window center (rintf == jnp.round, half-to-even)
    const float2 off2 = *(const float2*)&moff[(size_t)(p * NHD + g) * 2];
    const int cy = y + (int)rintf(off2.x);
    const int cx = x + (int)rintf(off2.y);

    const int chBase = g * CH + lig * 4;

    // clamped row/col element-offsets; chBase folded into the row term
    int pyW[7], pxc[7];
#pragma unroll
    for (int i = 0; i < 7; i++) {
        const int py = min(max(cy + i - RR, 0), HH - 1);
        const int px = min(max(cx + i - RR, 0), WW - 1);
        pyW[i] = (base + py * WW) * CC + chBase;
        pxc[i] = px * CC;
    }

    const float4 q4 = *(const float4*)(qp + (size_t)p * CC + chBase);

    const bool b0 = (lig & 1) != 0;
    const bool b1 = (lig & 2) != 0;
    const bool b2 = (lig & 4) != 0;
    const int  gbase = lane & 24;   // first lane of this head group

    float w_own[6];
    float s = 0.f;
    float4 acc = make_float4(0.f, 0.f, 0.f, 0.f);

#pragma unroll
    for (int j = 0; j < 6; j++) {
        // ---- shared addresses for this group (k and v gathers) --------------
        int offs[8];
#pragma unroll
        for (int t = 0; t < 8; t++) {
            const int kk = j * 8 + t;
            offs[t] = pyW[kk / 7] + pxc[kk % 7];
        }

        // ---- 8 k-gathers + per-lane partial L1 distances ---------------------
        float pd[8];
#pragma unroll
        for (int t = 0; t < 8; t++) {
            const float4 k4 = *(const float4*)(kp + offs[t]);
            pd[t] = fabsf(q4.x - k4.x) + fabsf(q4.y - k4.y)
                  + fabsf(q4.z - k4.z) + fabsf(q4.w - k4.w);
        }

        // ---- transposed butterfly: lane lig ends with full d of slot 8j+lig --
        float r4[4];
#pragma unroll
        for (int t = 0; t < 4; t++) {
            const float keep = b0 ? pd[2 * t + 1] : pd[2 * t];
            const float send = b0 ? pd[2 * t]     : pd[2 * t + 1];
            r4[t] = keep + __shfl_xor_sync(0xffffffffu, send, 1);
        }
        float r2[2];
#pragma unroll
        for (int t = 0; t < 2; t++) {
            const float keep = b1 ? r4[2 * t + 1] : r4[2 * t];
            const float send = b1 ? r4[2 * t]     : r4[2 * t + 1];
            r2[t] = keep + __shfl_xor_sync(0xffffffffu, send, 2);
        }
        const float keep = b2 ? r2[1] : r2[0];
        const float send = b2 ? r2[0] : r2[1];
        const float d = keep + __shfl_xor_sync(0xffffffffu, send, 4);

        const float w = __expf(-d);   // weight of owned slot 8j+lig
        s += w;
        w_own[j] = w;

        // ---- v accumulation: broadcast each slot's w from its owner lane ----
#pragma unroll
        for (int t = 0; t < 8; t++) {
            const float wt = __shfl_sync(0xffffffffu, w, gbase | t);
            const float4 v4 = *(const float4*)(vp + offs[t]);
            acc.x = fmaf(wt, v4.x, acc.x);
            acc.y = fmaf(wt, v4.y, acc.y);
            acc.z = fmaf(wt, v4.z, acc.z);
            acc.w = fmaf(wt, v4.w, acc.w);
        }
    }

    // ---- remainder slot 48 (row 6, col 6) ------------------------------------
    float w48;
    {
        const int off48 = pyW[6] + pxc[6];
        const float4 k4 = *(const float4*)(kp + off48);
        float d = fabsf(q4.x - k4.x) + fabsf(q4.y - k4.y)
                + fabsf(q4.z - k4.z) + fabsf(q4.w - k4.w);
        d += __shfl_xor_sync(0xffffffffu, d, 1);
        d += __shfl_xor_sync(0xffffffffu, d, 2);
        d += __shfl_xor_sync(0xffffffffu, d, 4);
        w48 = __expf(-d);                        // full weight on all 8 lanes
        const float4 v4 = *(const float4*)(vp + off48);
        acc.x = fmaf(w48, v4.x, acc.x);
        acc.y = fmaf(w48, v4.y, acc.y);
        acc.z = fmaf(w48, v4.z, acc.z);
        acc.w = fmaf(w48, v4.w, acc.w);
    }

    // ---- normalization --------------------------------------------------------
    // per-lane s covers its 6 owned slots; reduce over the head group, add 48
    s += __shfl_xor_sync(0xffffffffu, s, 1);
    s += __shfl_xor_sync(0xffffffffu, s, 2);
    s += __shfl_xor_sync(0xffffffffu, s, 4);
    s += w48;
    const float inv = 1.f / s;

    float* aout = attn_out + (size_t)(p * NHD + g) * KWIN;
#pragma unroll
    for (int j = 0; j < 6; j++) aout[j * 8 + lig] = w_own[j] * inv;
    if (lig == 0) aout[48] = w48 * inv;

    acc.x *= inv; acc.y *= inv; acc.z *= inv; acc.w *= inv;
    *(float4*)(out + (size_t)p * CC + chBase) = acc;
}

extern "C" void kernel_launch(void* const* d_in, const int* in_sizes, int n_in,
                              void* d_out, int out_size) {
    const float* moff = (const float*)d_in[0];   // [B,N,h,2]
    const float* q    = (const float*)d_in[1];   // [B,N,C]
    const float* k    = (const float*)d_in[2];
    const float* v    = (const float*)d_in[3];

    float* out = (float*)d_out;                  // output [B,N,C] first...
    const int qElems = in_sizes[1];              // B*N*C
    float* attn_out = out + qElems;              // ...then attn_out [B,N,h,K]

    const int items = in_sizes[0] / 2;           // B*N*h
    const int totalWarps = items / 4;            // 4 heads per warp
    const int threads = 256;
    const int blocks = (totalWarps * 32) / threads;   // 2048

    match_attn_kernel<<<blocks, threads>>>(moff, q, k, v, out, attn_out);
}